// round 2
// baseline (speedup 1.0000x reference)
#include <cuda_runtime.h>
#include <math.h>

// Problem constants
#define BB   4
#define CIN  256
#define CK   448
#define NN   4096
#define BM   32
#define BN   32
#define NEGV (-1e15f)
#define EPSV 1e-5f

// Scratch (device globals — no cudaMalloc allowed)
__device__ float g_Fq[(size_t)BB * NN * CK];   // [b][n][ck]  query proj
__device__ float g_G [(size_t)BB * NN * CK];   // [b][n][ck]  key proj (token-major)
__device__ float g_Hv[(size_t)BB * NN * CIN];  // [b][n][c]   value proj
__device__ float g_cstat[BB * CIN * 2];        // per (b,c): mean, 1/sqrt(var+eps)

// ---------------------------------------------------------------------------
// 1x1 conv projection: out[b][n][o] = sum_c in[b][c][n] * W[o][c] + bias[o]
// Block: 256 threads, covers 512 n (2 per thread) x 32 o. W tile staged in smem.
// ---------------------------------------------------------------------------
__global__ __launch_bounds__(256) void proj_kernel(
    const float* __restrict__ in, const float* __restrict__ Wm,
    const float* __restrict__ bias, float* __restrict__ out,
    int Cin, int Cout)
{
    const int b  = blockIdx.z;
    const int o0 = blockIdx.y * 32;
    const int n0 = blockIdx.x * 512;
    const int t  = threadIdx.x;

    __shared__ float Ws[32][65];

    float acc1[32], acc2[32];
#pragma unroll
    for (int o = 0; o < 32; o++) { acc1[o] = 0.f; acc2[o] = 0.f; }

    const float* inb = in + (size_t)b * Cin * NN;

    for (int c0 = 0; c0 < Cin; c0 += 64) {
        __syncthreads();
        for (int e = t; e < 32 * 64; e += 256) {
            int o = e >> 6, c = e & 63;
            Ws[o][c] = Wm[(size_t)(o0 + o) * Cin + c0 + c];
        }
        __syncthreads();
#pragma unroll 4
        for (int c = 0; c < 64; c++) {
            float x1 = inb[(size_t)(c0 + c) * NN + n0 + t];
            float x2 = inb[(size_t)(c0 + c) * NN + n0 + 256 + t];
#pragma unroll
            for (int o = 0; o < 32; o++) {
                float w = Ws[o][c];
                acc1[o] = fmaf(x1, w, acc1[o]);
                acc2[o] = fmaf(x2, w, acc2[o]);
            }
        }
    }

    float* ob = out + (size_t)b * NN * Cout;
#pragma unroll
    for (int o = 0; o < 32; o++) {
        float bv = bias[o0 + o];
        ob[(size_t)(n0 + t) * Cout + o0 + o]       = acc1[o] + bv;
        ob[(size_t)(n0 + 256 + t) * Cout + o0 + o] = acc2[o] + bv;
    }
}

// ---------------------------------------------------------------------------
// Content stats for mean_variance_norm: per (b,c) mean + 1/sqrt(var_unbiased+eps)
// ---------------------------------------------------------------------------
__global__ __launch_bounds__(256) void cstat_kernel(const float* __restrict__ content)
{
    const int bc = blockIdx.x;
    const float* p = content + (size_t)bc * NN;
    float s = 0.f, s2 = 0.f;
    for (int i = threadIdx.x; i < NN; i += 256) {
        float v = p[i];
        s += v;
        s2 = fmaf(v, v, s2);
    }
    __shared__ float rs[256], rs2[256];
    rs[threadIdx.x] = s; rs2[threadIdx.x] = s2;
    __syncthreads();
    for (int st = 128; st > 0; st >>= 1) {
        if (threadIdx.x < st) {
            rs[threadIdx.x]  += rs[threadIdx.x + st];
            rs2[threadIdx.x] += rs2[threadIdx.x + st];
        }
        __syncthreads();
    }
    if (threadIdx.x == 0) {
        float mean = rs[0] / NN;
        float var  = (rs2[0] - (float)NN * mean * mean) / (float)(NN - 1);
        g_cstat[bc * 2]     = mean;
        g_cstat[bc * 2 + 1] = 1.f / sqrtf(var + EPSV);
    }
}

// ---------------------------------------------------------------------------
// Fused flash attention + weighted mean/std + mvn epilogue.
// Grid: (NN/BM, BB), 256 threads. One CTA owns BM=32 queries; loops over
// BN=32-key tiles with online softmax. Accumulators (mean, m2) live in regs:
// thread t owns query qi=t>>3, channels c = (t&7) + 8k, k=0..31.
// ---------------------------------------------------------------------------
__global__ __launch_bounds__(256, 1) void attn_kernel(
    const float* __restrict__ content,
    const int*   __restrict__ cmask,
    const int*   __restrict__ smask,
    float*       __restrict__ out)
{
    const int b  = blockIdx.y;
    const int q0 = blockIdx.x * BM;
    const int t  = threadIdx.x;

    extern __shared__ float smem[];
    float* Qs        = smem;              // [32][449]
    float* Ks        = Qs + 32 * 449;     // [32][449]
    float* Vs        = Ks + 32 * 449;     // [32][257]
    float* Ps        = Vs + 32 * 257;     // [32][33]
    float* row_m     = Ps + 32 * 33;      // [32]
    float* row_scale = row_m + 32;        // [32]
    float* row_l     = row_scale + 32;    // [32]
    int*   sflag     = (int*)(row_l + 32);// [32]

    // Load Q tile (stays resident)
    for (int e = t; e < 32 * CK; e += 256) {
        int i = e / CK, k = e - i * CK;
        Qs[i * 449 + k] = g_Fq[((size_t)b * NN + q0 + i) * CK + k];
    }
    if (t < 32) { row_m[t] = -INFINITY; row_l[t] = 0.f; }

    // S-phase mapping: 16x16 thread grid, 2x2 micro-tile
    const int ti = t >> 4, tj = t & 15;
    const int i0 = 2 * ti, i1 = 2 * ti + 1;
    const int j0 = 2 * tj, j1 = 2 * tj + 1;
    const bool cm0 = cmask[b * NN + q0 + i0] != 0;
    const bool cm1 = cmask[b * NN + q0 + i1] != 0;

    // PV-phase mapping
    const int qi = t >> 3, g = t & 7;

    float accm[32], acc2[32];
#pragma unroll
    for (int k = 0; k < 32; k++) { accm[k] = 0.f; acc2[k] = 0.f; }

    __syncthreads();

    for (int kt = 0; kt < NN / BN; kt++) {
        const int k0 = kt * BN;

        // Load K / V tiles + style-mask flags
        for (int e = t; e < 32 * CK; e += 256) {
            int j = e / CK, k = e - j * CK;
            Ks[j * 449 + k] = g_G[((size_t)b * NN + k0 + j) * CK + k];
        }
        for (int e = t; e < 32 * CIN; e += 256) {
            int j = e >> 8, c = e & 255;
            Vs[j * 257 + c] = g_Hv[((size_t)b * NN + k0 + j) * CIN + c];
        }
        if (t < 32) sflag[t] = (smask[b * NN + k0 + t] == 0) ? 1 : 0;
        __syncthreads();

        // ---- S tile: 2x2 micro dot-products over CK=448 ----
        float s00 = 0.f, s01 = 0.f, s10 = 0.f, s11 = 0.f;
        const float* qa = Qs + i0 * 449;
        const float* qb = Qs + i1 * 449;
        const float* ka = Ks + j0 * 449;
        const float* kb = Ks + j1 * 449;
#pragma unroll 4
        for (int k = 0; k < CK; k++) {
            float q0v = qa[k], q1v = qb[k], k0v = ka[k], k1v = kb[k];
            s00 = fmaf(q0v, k0v, s00); s01 = fmaf(q0v, k1v, s01);
            s10 = fmaf(q1v, k0v, s10); s11 = fmaf(q1v, k1v, s11);
        }
        if (cm0) { if (sflag[j0]) s00 = NEGV; if (sflag[j1]) s01 = NEGV; }
        if (cm1) { if (sflag[j0]) s10 = NEGV; if (sflag[j1]) s11 = NEGV; }

        // ---- online softmax: row reductions within 16-lane half-warps ----
        float m0 = fmaxf(s00, s01), m1 = fmaxf(s10, s11);
#pragma unroll
        for (int off = 1; off < 16; off <<= 1) {
            m0 = fmaxf(m0, __shfl_xor_sync(0xffffffffu, m0, off));
            m1 = fmaxf(m1, __shfl_xor_sync(0xffffffffu, m1, off));
        }
        float om0 = row_m[i0], om1 = row_m[i1];
        float nm0 = fmaxf(om0, m0), nm1 = fmaxf(om1, m1);
        float p00 = __expf(s00 - nm0), p01 = __expf(s01 - nm0);
        float p10 = __expf(s10 - nm1), p11 = __expf(s11 - nm1);
        Ps[i0 * 33 + j0] = p00; Ps[i0 * 33 + j1] = p01;
        Ps[i1 * 33 + j0] = p10; Ps[i1 * 33 + j1] = p11;
        float r0 = p00 + p01, r1 = p10 + p11;
#pragma unroll
        for (int off = 1; off < 16; off <<= 1) {
            r0 += __shfl_xor_sync(0xffffffffu, r0, off);
            r1 += __shfl_xor_sync(0xffffffffu, r1, off);
        }
        __syncwarp();
        if (tj == 0) {
            float sc0 = __expf(om0 - nm0);
            float sc1 = __expf(om1 - nm1);
            row_scale[i0] = sc0; row_scale[i1] = sc1;
            row_l[i0] = row_l[i0] * sc0 + r0;
            row_l[i1] = row_l[i1] * sc1 + r1;
            row_m[i0] = nm0; row_m[i1] = nm1;
        }
        __syncthreads();

        // ---- PV: rescale accumulators, add p * V and p * V^2 ----
        float sc = row_scale[qi];
#pragma unroll
        for (int k = 0; k < 32; k++) { accm[k] *= sc; acc2[k] *= sc; }
        const float* ppr = Ps + qi * 33;
#pragma unroll 2
        for (int j = 0; j < BN; j++) {
            float p = ppr[j];
            const float* vr = Vs + j * 257 + g;
#pragma unroll
            for (int k = 0; k < 32; k++) {
                float v  = vr[8 * k];
                float pv = p * v;
                accm[k] += pv;
                acc2[k]  = fmaf(pv, v, acc2[k]);
            }
        }
        __syncthreads();
    }

    // ---- epilogue: normalize, std = sqrt(relu(m2 - mean^2)), blend with mvn(content) ----
    const int n = q0 + qi;
    float invl = 1.f / row_l[qi];
#pragma unroll
    for (int k = 0; k < 32; k++) {
        int c = g + 8 * k;
        float mean = accm[k] * invl;
        float m2   = acc2[k] * invl;
        float sd   = sqrtf(fmaxf(m2 - mean * mean, 0.f));
        size_t ci  = (size_t)(b * CIN + c);
        float x    = content[ci * NN + n];
        float cmn  = g_cstat[2 * ci];
        float cis  = g_cstat[2 * ci + 1];
        out[ci * NN + n] = sd * ((x - cmn) * cis) + mean;
    }
}

// ---------------------------------------------------------------------------
extern "C" void kernel_launch(void* const* d_in, const int* in_sizes, int n_in,
                              void* d_out, int out_size)
{
    const float* content = (const float*)d_in[0];
    const float* style   = (const float*)d_in[1];
    const float* ckey    = (const float*)d_in[2];
    const float* skey    = (const float*)d_in[3];
    const int*   cmask   = (const int*)d_in[4];
    const int*   smask   = (const int*)d_in[5];
    const float* Wf      = (const float*)d_in[6];
    const float* bf      = (const float*)d_in[7];
    const float* Wg      = (const float*)d_in[8];
    const float* bg      = (const float*)d_in[9];
    const float* Wh      = (const float*)d_in[10];
    const float* bh      = (const float*)d_in[11];
    float* out = (float*)d_out;

    float *fq, *gp, *hv;
    cudaGetSymbolAddress((void**)&fq, g_Fq);
    cudaGetSymbolAddress((void**)&gp, g_G);
    cudaGetSymbolAddress((void**)&hv, g_Hv);

    dim3 pgK(NN / 512, CK / 32, BB);
    proj_kernel<<<pgK, 256>>>(ckey, Wf, bf, fq, CK, CK);
    proj_kernel<<<pgK, 256>>>(skey, Wg, bg, gp, CK, CK);
    dim3 pgV(NN / 512, CIN / 32, BB);
    proj_kernel<<<pgV, 256>>>(style, Wh, bh, hv, CIN, CIN);

    cstat_kernel<<<BB * CIN, 256>>>(content);

    int smem_bytes = (32 * 449 * 2 + 32 * 257 + 32 * 33 + 3 * 32 + 32) * (int)sizeof(float);
    cudaFuncSetAttribute(attn_kernel, cudaFuncAttributeMaxDynamicSharedMemorySize, smem_bytes);
    attn_kernel<<<dim3(NN / BM, BB), 256, smem_bytes>>>(content, cmask, smask, out);
}